// round 2
// baseline (speedup 1.0000x reference)
#include <cuda_runtime.h>
#include <math_constants.h>

#define N_PTS 16384
#define C_DIM 64
#define K_NN 16
#define M_OUT 256   // C*R

__device__ float g_norms[N_PTS];
__device__ int   g_knn[N_PTS * K_NN];

// ---------------------------------------------------------------------------
// Kernel 0: squared norms
// ---------------------------------------------------------------------------
__global__ __launch_bounds__(256) void norms_kernel(const float* __restrict__ x) {
    int i = blockIdx.x * 256 + threadIdx.x;
    const float4* xv = (const float4*)(x + (size_t)i * C_DIM);
    float s = 0.f;
#pragma unroll
    for (int d = 0; d < 16; ++d) {
        float4 v = xv[d];
        s += v.x * v.x + v.y * v.y + v.z * v.z + v.w * v.w;
    }
    g_norms[i] = s;
}

// ---------------------------------------------------------------------------
// Kernel 1: fused distance + top-16 selection.
// 1 thread per query, x_q in registers, candidate tile broadcast from smem.
// ---------------------------------------------------------------------------
#define QT 128
#define JT 128

__global__ __launch_bounds__(128) void knn_kernel(const float* __restrict__ x) {
    __shared__ float4 sc[JT * 16];   // candidate tile, 32 KB
    __shared__ float  sn[JT];        // candidate norms

    int t = threadIdx.x;
    int q = blockIdx.x * QT + t;

    float4 xq[16];
    const float4* xv = (const float4*)(x + (size_t)q * C_DIM);
#pragma unroll
    for (int d = 0; d < 16; ++d) xq[d] = xv[d];
    float nq = g_norms[q];

    float bd[16];
    int   bi[16];
#pragma unroll
    for (int s = 0; s < 16; ++s) { bd[s] = CUDART_INF_F; bi[s] = 0; }

    for (int jt = 0; jt < N_PTS; jt += JT) {
        __syncthreads();
        const float4* src = (const float4*)(x + (size_t)jt * C_DIM);
#pragma unroll
        for (int i = 0; i < 16; ++i) sc[t + i * 128] = src[t + i * 128];
        sn[t] = g_norms[jt + t];
        __syncthreads();

#pragma unroll 1
        for (int j = 0; j < JT; ++j) {
            float a0 = 0.f, a1 = 0.f, a2 = 0.f, a3 = 0.f;
#pragma unroll
            for (int d = 0; d < 16; ++d) {
                float4 c = sc[j * 16 + d];           // broadcast across warp
                a0 = fmaf(xq[d].x, c.x, a0);
                a1 = fmaf(xq[d].y, c.y, a1);
                a2 = fmaf(xq[d].z, c.z, a2);
                a3 = fmaf(xq[d].w, c.w, a3);
            }
            float dot = (a0 + a1) + (a2 + a3);
            float d2 = nq + sn[j] - 2.0f * dot;
            int gj = jt + j;
            if (d2 < bd[15] && gj != q) {
                // bubble-insert into sorted-ascending register heap
                float cd = d2; int ci = gj;
#pragma unroll
                for (int s = 0; s < 16; ++s) {
                    if (cd < bd[s]) {
                        float td = bd[s]; bd[s] = cd; cd = td;
                        int   ti = bi[s]; bi[s] = ci; ci = ti;
                    }
                }
            }
        }
    }
#pragma unroll
    for (int s = 0; s < 16; ++s) g_knn[q * K_NN + s] = bi[s];
}

// ---------------------------------------------------------------------------
// Kernel 2: gather + edge-MLP + relu + max over K + pixel-shuffle store.
// W resident in smem (128 KB). Warp per query; lane owns 8 output columns.
// 4-neighbor x 8-column register tile amortizes smem traffic.
// ---------------------------------------------------------------------------
#define MLP_SMEM_FLOATS (32768 + 8 * 2048)   // W + 8 warp feat tiles

__global__ __launch_bounds__(256) void mlp_kernel(const float* __restrict__ x,
                                                  const float* __restrict__ W,
                                                  const float* __restrict__ b,
                                                  float* __restrict__ y) {
    extern __shared__ float smem[];
    float* sW    = smem;            // 128x256
    float* sfeat = smem + 32768;    // 8 warps x (16x128)

    int tid  = threadIdx.x;
    int warp = tid >> 5;
    int lane = tid & 31;

    // stage W into smem once
    {
        const float4* Wv = (const float4*)W;
        float4* sWv = (float4*)sW;
        for (int i = tid; i < 8192; i += 256) sWv[i] = Wv[i];
    }
    float bb[8];
#pragma unroll
    for (int k = 0; k < 8; ++k) bb[k] = b[lane * 8 + k];
    __syncthreads();

    float* f = sfeat + warp * 2048;
    const float4* f4  = (const float4*)f;
    const float4* sW4 = (const float4*)sW;

    for (int qg = blockIdx.x; qg < N_PTS / 8; qg += gridDim.x) {
        int q = qg * 8 + warp;

        // gather feat[n][0:64]=x_i, feat[n][64:128]=x_j - x_i
        float xi0 = x[(size_t)q * 64 + lane];
        float xi1 = x[(size_t)q * 64 + 32 + lane];
#pragma unroll 1
        for (int n = 0; n < 16; ++n) {
            int j = g_knn[q * 16 + n];
            float v0 = x[(size_t)j * 64 + lane];
            float v1 = x[(size_t)j * 64 + 32 + lane];
            f[n * 128 + lane]      = xi0;
            f[n * 128 + 32 + lane] = xi1;
            f[n * 128 + 64 + lane] = v0 - xi0;
            f[n * 128 + 96 + lane] = v1 - xi1;
        }
        __syncwarp();

        float vmax[8];
#pragma unroll
        for (int k = 0; k < 8; ++k) vmax[k] = 0.f;   // relu >= 0

#pragma unroll 1
        for (int ch = 0; ch < 4; ++ch) {             // 4 neighbors per chunk
            float acc[4][8];
#pragma unroll
            for (int n = 0; n < 4; ++n)
#pragma unroll
                for (int k = 0; k < 8; ++k) acc[n][k] = bb[k];

#pragma unroll 2
            for (int d = 0; d < 128; d += 4) {
                float4 fv[4];
#pragma unroll
                for (int n = 0; n < 4; ++n)
                    fv[n] = f4[(ch * 4 + n) * 32 + (d >> 2)];   // broadcast
#pragma unroll
                for (int dd = 0; dd < 4; ++dd) {
                    float4 w0 = sW4[(d + dd) * 64 + lane * 2];
                    float4 w1 = sW4[(d + dd) * 64 + lane * 2 + 1];
#pragma unroll
                    for (int n = 0; n < 4; ++n) {
                        float fe = (dd == 0) ? fv[n].x : (dd == 1) ? fv[n].y
                                 : (dd == 2) ? fv[n].z : fv[n].w;
                        acc[n][0] = fmaf(fe, w0.x, acc[n][0]);
                        acc[n][1] = fmaf(fe, w0.y, acc[n][1]);
                        acc[n][2] = fmaf(fe, w0.z, acc[n][2]);
                        acc[n][3] = fmaf(fe, w0.w, acc[n][3]);
                        acc[n][4] = fmaf(fe, w1.x, acc[n][4]);
                        acc[n][5] = fmaf(fe, w1.y, acc[n][5]);
                        acc[n][6] = fmaf(fe, w1.z, acc[n][6]);
                        acc[n][7] = fmaf(fe, w1.w, acc[n][7]);
                    }
                }
            }
#pragma unroll
            for (int n = 0; n < 4; ++n)
#pragma unroll
                for (int k = 0; k < 8; ++k)
                    vmax[k] = fmaxf(vmax[k], fmaxf(acc[n][k], 0.f));
        }

        // m = lane*8+k ; c = m>>2 ; r = m&3 ; y[(q*4+r)*64 + c]
#pragma unroll
        for (int r = 0; r < 4; ++r) {
            float2 v = make_float2(vmax[r], vmax[4 + r]);
            ((float2*)(y + (size_t)(q * 4 + r) * 64))[lane] = v;
        }
        __syncwarp();
    }
}

// ---------------------------------------------------------------------------
extern "C" void kernel_launch(void* const* d_in, const int* in_sizes, int n_in,
                              void* d_out, int out_size) {
    const float* x = (const float*)d_in[0];
    const float* W = (const float*)d_in[1];
    const float* b = (const float*)d_in[2];
    float* y = (float*)d_out;

    norms_kernel<<<N_PTS / 256, 256>>>(x);
    knn_kernel<<<N_PTS / QT, QT>>>(x);

    cudaFuncSetAttribute(mlp_kernel,
                         cudaFuncAttributeMaxDynamicSharedMemorySize,
                         MLP_SMEM_FLOATS * sizeof(float));
    mlp_kernel<<<148, 256, MLP_SMEM_FLOATS * sizeof(float)>>>(x, W, b, y);
}